// round 2
// baseline (speedup 1.0000x reference)
#include <cuda_runtime.h>

#define NN   10000
#define EE   320000
#define RR   460
#define BB   30
#define DD   200
#define KTOT (BB * DD + DD)   // 6200

// ---- device scratch (no allocations allowed) ----
__device__ float g_A[(size_t)NN * KTOT];   // [H*inv_deg | x] rows
__device__ int   g_deg[NN];
__device__ int   g_off[NN + 1];
__device__ int   g_cur[NN];
__device__ int   g_esrc[EE];
__device__ int   g_erel[EE];

// packed fp32x2 FMA (SASS FFMA2) — exact fp32, 2 MACs per issue slot
__device__ __forceinline__ float2 f2fma(float2 a, float2 b, float2 c) {
    float2 d;
    asm("fma.rn.f32x2 %0, %1, %2, %3;"
        : "=l"(reinterpret_cast<unsigned long long&>(d))
        : "l"(reinterpret_cast<unsigned long long&>(a)),
          "l"(reinterpret_cast<unsigned long long&>(b)),
          "l"(reinterpret_cast<unsigned long long&>(c)));
    return d;
}

// ---------------- CSR build ----------------
__global__ void k_zero_deg() {
    int i = blockIdx.x * blockDim.x + threadIdx.x;
    if (i < NN) g_deg[i] = 0;
}

__global__ void k_count(const int* __restrict__ eidx) {
    int e = blockIdx.x * blockDim.x + threadIdx.x;
    if (e < EE) atomicAdd(&g_deg[eidx[EE + e]], 1);
}

__global__ void k_scan() {
    __shared__ int buf[1024];
    __shared__ int carry_s;
    int tid = threadIdx.x;
    if (tid == 0) carry_s = 0;
    __syncthreads();
    for (int base = 0; base < NN; base += 1024) {
        int i = base + tid;
        int v = (i < NN) ? g_deg[i] : 0;
        buf[tid] = v;
        __syncthreads();
        for (int off = 1; off < 1024; off <<= 1) {
            int t = (tid >= off) ? buf[tid - off] : 0;
            __syncthreads();
            buf[tid] += t;
            __syncthreads();
        }
        int excl = carry_s + buf[tid] - v;
        if (i < NN) { g_off[i] = excl; g_cur[i] = excl; }
        __syncthreads();
        if (tid == 0) carry_s += buf[1023];
        __syncthreads();
    }
    if (tid == 0) g_off[NN] = carry_s;
}

__global__ void k_fill(const int* __restrict__ eidx, const int* __restrict__ etype) {
    int e = blockIdx.x * blockDim.x + threadIdx.x;
    if (e < EE) {
        int t = eidx[EE + e];
        int p = atomicAdd(&g_cur[t], 1);
        g_esrc[p] = eidx[e];
        g_erel[p] = etype[e];
    }
}

// ---------------- aggregation: H[n,b,d] = inv_deg * sum_{e->n} coeff[r_e,b]*x[src_e,d] ----------------
// 128 threads; threads 0..99 each own a d-pair (2t, 2t+1). f32x2 FMA throughout.
#define AGG_T 128
#define EB    32
__global__ __launch_bounds__(AGG_T) void k_agg(const float* __restrict__ x,
                                               const float* __restrict__ coeff) {
    __shared__ float2 sC2[EB][BB];   // coeff duplicated (c,c)
    __shared__ int    sSrc[EB];
    __shared__ int    sRel[EB];
    int n   = blockIdx.x;
    int tid = threadIdx.x;
    int start = g_off[n], end = g_off[n + 1];
    int deg = end - start;
    float inv = 1.0f / (float)(deg > 1 ? deg : 1);

    float2 acc[BB];
#pragma unroll
    for (int b = 0; b < BB; b++) acc[b] = make_float2(0.f, 0.f);

    bool active = tid < DD / 2;
    for (int e0 = start; e0 < end; e0 += EB) {
        int nb = min(EB, end - e0);
        __syncthreads();                       // protect smem from prior-iter readers
        if (tid < nb) {
            sSrc[tid] = g_esrc[e0 + tid];
            sRel[tid] = g_erel[e0 + tid];
        }
        __syncthreads();
        for (int i = tid; i < nb * BB; i += AGG_T) {
            int le = i / BB, b = i - le * BB;
            float c = coeff[sRel[le] * BB + b];
            sC2[le][b] = make_float2(c, c);
        }
        __syncthreads();
        if (active) {
            for (int le = 0; le < nb; le++) {
                float2 xv = *(const float2*)(x + (size_t)sSrc[le] * DD + 2 * tid);
#pragma unroll
                for (int b = 0; b < BB; b++) acc[b] = f2fma(sC2[le][b], xv, acc[b]);
            }
        }
    }
    if (active) {
        size_t row = (size_t)n * KTOT;
        float2* __restrict__ Ar = (float2*)(g_A + row);
#pragma unroll
        for (int b = 0; b < BB; b++) {
            Ar[(b * DD) / 2 + tid] = make_float2(acc[b].x * inv, acc[b].y * inv);
        }
        // self-loop K-columns
        Ar[(BB * DD) / 2 + tid] = *(const float2*)(x + (size_t)n * DD + 2 * tid);
    }
}

// ---------------- GEMM: out(10000x200) = g_A(10000x6200) @ [weight;self_weight](6200x200) + bias ----------------
// BM=40, BN=200 (100 pairs), BK=20, 200 threads, per-thread 5 rows x 4 col-pairs via FFMA2.
#define BM 40
#define BK 20
#define GT 200
__global__ __launch_bounds__(GT) void k_gemm(const float* __restrict__ weight,
                                             const float* __restrict__ selfw,
                                             const float* __restrict__ bias,
                                             float* __restrict__ out) {
    __shared__ float2 sA[BK][BM];    // duplicated (a,a): 6.4 KB
    __shared__ float2 sB[BK][DD / 2]; // 16 KB
    int tid = threadIdx.x;
    int m0  = blockIdx.x * BM;
    int tr  = tid / 25;   // 0..7
    int tc  = tid % 25;   // 0..24

    float2 acc[5][4];
#pragma unroll
    for (int i = 0; i < 5; i++)
#pragma unroll
        for (int j = 0; j < 4; j++) acc[i][j] = make_float2(0.f, 0.f);

    for (int k0 = 0; k0 < KTOT; k0 += BK) {
        // A tile: BM*BK = 800 floats, 4 per thread
#pragma unroll
        for (int t = 0; t < 4; t++) {
            int ii = tid + t * GT;
            int r = ii / BK, kk = ii - r * BK;
            float v = g_A[(size_t)(m0 + r) * KTOT + k0 + kk];
            sA[kk][r] = make_float2(v, v);
        }
        // B tile: BK*DD = 4000 floats = 2000 float2, 10 per thread; k=6000 boundary is BK-aligned
        const float* Bsrc = (k0 < BB * DD) ? (weight + (size_t)k0 * DD)
                                           : (selfw + (size_t)(k0 - BB * DD) * DD);
#pragma unroll
        for (int t = 0; t < 10; t++) {
            int ii = tid + t * GT;
            int kk = ii / (DD / 2), c = ii - kk * (DD / 2);
            sB[kk][c] = *(const float2*)(Bsrc + kk * DD + 2 * c);
        }
        __syncthreads();
#pragma unroll
        for (int kk = 0; kk < BK; kk++) {
            float2 a[5], b[4];
#pragma unroll
            for (int i = 0; i < 5; i++) a[i] = sA[kk][tr + 8 * i];
#pragma unroll
            for (int j = 0; j < 4; j++) b[j] = sB[kk][tc + 25 * j];
#pragma unroll
            for (int i = 0; i < 5; i++)
#pragma unroll
                for (int j = 0; j < 4; j++) acc[i][j] = f2fma(a[i], b[j], acc[i][j]);
        }
        __syncthreads();
    }
#pragma unroll
    for (int j = 0; j < 4; j++) {
        int cp = tc + 25 * j;                 // column pair index
        float2 bv = *(const float2*)(bias + 2 * cp);
#pragma unroll
        for (int i = 0; i < 5; i++) {
            float2 r = acc[i][j];
            r.x += bv.x; r.y += bv.y;
            *(float2*)(out + (size_t)(m0 + tr + 8 * i) * DD + 2 * cp) = r;
        }
    }
}

extern "C" void kernel_launch(void* const* d_in, const int* in_sizes, int n_in,
                              void* d_out, int out_size) {
    const float* x      = (const float*)d_in[0];
    const float* weight = (const float*)d_in[1];
    const float* coeff  = (const float*)d_in[2];
    const float* selfw  = (const float*)d_in[3];
    const float* bias   = (const float*)d_in[4];
    const int*   eidx   = (const int*)d_in[5];
    const int*   etype  = (const int*)d_in[6];
    float*       out    = (float*)d_out;

    k_zero_deg<<<(NN + 255) / 256, 256>>>();
    k_count<<<(EE + 255) / 256, 256>>>(eidx);
    k_scan<<<1, 1024>>>();
    k_fill<<<(EE + 255) / 256, 256>>>(eidx, etype);
    k_agg<<<NN, AGG_T>>>(x, coeff);
    k_gemm<<<NN / BM, GT>>>(weight, selfw, bias, out);
}

// round 4
// speedup vs baseline: 2.3871x; 2.3871x over previous
#include <cuda_runtime.h>
#include <cuda_bf16.h>
#include <cstdint>

#define NN   10000
#define EE   320000
#define RR   460
#define BB   30
#define DD   200
#define KTOT 6200
#define KPAD 6208            // multiple of 64
#define MPAD 10112           // 158 * 64
#define NPAD 224             // multiple of 16
#define KHALF 3104           // KPAD / 2
#define NCHUNK 97            // KHALF / 32

// ---- device scratch (zero-initialized; pad rows/cols never written -> stay 0) ----
__device__ __nv_bfloat16 g_Ah[(size_t)MPAD * KPAD];
__device__ __nv_bfloat16 g_Al[(size_t)MPAD * KPAD];
__device__ __nv_bfloat16 g_Bh[(size_t)NPAD * KPAD];   // B^T: n-major rows, k cols
__device__ __nv_bfloat16 g_Bl[(size_t)NPAD * KPAD];
__device__ int g_deg[NN];
__device__ int g_off[NN + 1];
__device__ int g_cur[NN];
__device__ int g_esrc[EE];
__device__ int g_erel[EE];

// ---------------- helpers ----------------
__device__ __forceinline__ uint32_t smem_u32(const void* p) {
    uint32_t a;
    asm("{ .reg .u64 t; cvta.to.shared.u64 t, %1; cvt.u32.u64 %0, t; }" : "=r"(a) : "l"(p));
    return a;
}
__device__ __forceinline__ void ldsm4(uint32_t* r, uint32_t a) {
    asm volatile("ldmatrix.sync.aligned.m8n8.x4.shared.b16 {%0,%1,%2,%3}, [%4];"
                 : "=r"(r[0]), "=r"(r[1]), "=r"(r[2]), "=r"(r[3]) : "r"(a));
}
__device__ __forceinline__ void mma16816(float* c, const uint32_t* a, uint32_t b0, uint32_t b1) {
    asm volatile(
        "mma.sync.aligned.m16n8k16.row.col.f32.bf16.bf16.f32 "
        "{%0,%1,%2,%3}, {%4,%5,%6,%7}, {%8,%9}, {%0,%1,%2,%3};"
        : "+f"(c[0]), "+f"(c[1]), "+f"(c[2]), "+f"(c[3])
        : "r"(a[0]), "r"(a[1]), "r"(a[2]), "r"(a[3]), "r"(b0), "r"(b1));
}
__device__ __forceinline__ void cpasync16(uint32_t sa, const void* gp) {
    asm volatile("cp.async.cg.shared.global [%0], [%1], 16;" :: "r"(sa), "l"(gp));
}

// ---------------- CSR build ----------------
__global__ void k_zero_deg() {
    int i = blockIdx.x * blockDim.x + threadIdx.x;
    if (i < NN) g_deg[i] = 0;
}
__global__ void k_count(const int* __restrict__ eidx) {
    int e = blockIdx.x * blockDim.x + threadIdx.x;
    if (e < EE) atomicAdd(&g_deg[eidx[EE + e]], 1);
}
__global__ void k_scan() {
    __shared__ int buf[1024];
    __shared__ int carry_s;
    int tid = threadIdx.x;
    if (tid == 0) carry_s = 0;
    __syncthreads();
    for (int base = 0; base < NN; base += 1024) {
        int i = base + tid;
        int v = (i < NN) ? g_deg[i] : 0;
        buf[tid] = v;
        __syncthreads();
        for (int off = 1; off < 1024; off <<= 1) {
            int t = (tid >= off) ? buf[tid - off] : 0;
            __syncthreads();
            buf[tid] += t;
            __syncthreads();
        }
        int excl = carry_s + buf[tid] - v;
        if (i < NN) { g_off[i] = excl; g_cur[i] = excl; }
        __syncthreads();
        if (tid == 0) carry_s += buf[1023];
        __syncthreads();
    }
    if (tid == 0) g_off[NN] = carry_s;
}
__global__ void k_fill(const int* __restrict__ eidx, const int* __restrict__ etype) {
    int e = blockIdx.x * blockDim.x + threadIdx.x;
    if (e < EE) {
        int t = eidx[EE + e];
        int p = atomicAdd(&g_cur[t], 1);
        g_esrc[p] = eidx[e];
        g_erel[p] = etype[e];
    }
}

// ---------------- weight transpose + bf16 split ----------------
__global__ void k_prep_w(const float* __restrict__ w, const float* __restrict__ sw) {
    int i = blockIdx.x * blockDim.x + threadIdx.x;
    if (i >= DD * KPAD) return;
    int n = i / KPAD, k = i - n * KPAD;
    float v = 0.f;
    if (k < 6000)      v = w[(size_t)k * DD + n];
    else if (k < KTOT) v = sw[(size_t)(k - 6000) * DD + n];
    __nv_bfloat16 h = __float2bfloat16(v);
    __nv_bfloat16 l = __float2bfloat16(v - __bfloat162float(h));
    g_Bh[(size_t)n * KPAD + k] = h;
    g_Bl[(size_t)n * KPAD + k] = l;
}

// ---------------- out = bias (broadcast) ----------------
__global__ void k_init(const float* __restrict__ bias, float* __restrict__ out) {
    int i = blockIdx.x * blockDim.x + threadIdx.x;
    if (i < NN * DD) out[i] = bias[i % DD];
}

// ---------------- aggregation -> bf16 hi/lo A rows ----------------
#define AGG_T 224
#define EB    32
__global__ __launch_bounds__(AGG_T) void k_agg(const float* __restrict__ x,
                                               const float* __restrict__ coeff) {
    __shared__ float sC[EB][32];    // coeff padded to 32, float4-loadable
    __shared__ int   sSrc[EB];
    __shared__ int   sRel[EB];
    int n   = blockIdx.x;
    int tid = threadIdx.x;
    int start = g_off[n], end = g_off[n + 1];
    int deg = end - start;
    float inv = 1.0f / (float)(deg > 1 ? deg : 1);

    float acc[BB];
#pragma unroll
    for (int b = 0; b < BB; b++) acc[b] = 0.f;

    int d = tid;
    bool active = d < DD;
    for (int e0 = start; e0 < end; e0 += EB) {
        int nb = min(EB, end - e0);
        __syncthreads();
        if (tid < nb) { sSrc[tid] = g_esrc[e0 + tid]; sRel[tid] = g_erel[e0 + tid]; }
        __syncthreads();
        for (int i = tid; i < nb * 32; i += AGG_T) {
            int le = i >> 5, b = i & 31;
            sC[le][b] = (b < BB) ? coeff[sRel[le] * BB + b] : 0.f;
        }
        __syncthreads();
        if (active) {
            for (int le = 0; le < nb; le++) {
                float xv = x[(size_t)sSrc[le] * DD + d];
                float c[32];
                const float4* cp = (const float4*)sC[le];
#pragma unroll
                for (int q = 0; q < 8; q++) *(float4*)&c[4 * q] = cp[q];
#pragma unroll
                for (int b = 0; b < BB; b++) acc[b] = fmaf(c[b], xv, acc[b]);
            }
        }
    }
    if (active) {
        size_t row = (size_t)n * KPAD;
#pragma unroll
        for (int b = 0; b < BB; b++) {
            float v = acc[b] * inv;
            __nv_bfloat16 h = __float2bfloat16(v);
            g_Ah[row + b * DD + d] = h;
            g_Al[row + b * DD + d] = __float2bfloat16(v - __bfloat162float(h));
        }
        float v = x[(size_t)n * DD + d];
        __nv_bfloat16 h = __float2bfloat16(v);
        g_Ah[row + 6000 + d] = h;
        g_Al[row + 6000 + d] = __float2bfloat16(v - __bfloat162float(h));
    }
}

// ---------------- bf16 3-term MMA GEMM, K-split 2, atomic epilogue ----------------
// CTA: 128 thr (4 warps), tile m64 x n224, warp m32 x n112. K_block=32 elems.
#define GT     128
#define RS     80          // 64B data + 16B pad per row (conflict-free ldmatrix)
#define A_ARR  5120        // 64*RS
#define B_ARR  17920       // 224*RS
#define OFF_B  10240       // 2*A_ARR
#define STAGE  46080       // 2*A_ARR + 2*B_ARR
#define SMEM_G (2 * STAGE) // 92160

__global__ __launch_bounds__(GT, 2) void k_gemm(float* __restrict__ out) {
    extern __shared__ char smem[];
    uint32_t sb = smem_u32(smem);
    int tid = threadIdx.x, lane = tid & 31, wid = tid >> 5;
    int m0 = blockIdx.x * 64;
    int kbase = blockIdx.y * KHALF;
    int wm = wid & 1, wn = wid >> 1;

    const char* gA[2] = {(const char*)g_Ah, (const char*)g_Al};
    const char* gB[2] = {(const char*)g_Bh, (const char*)g_Bl};

    float acc[2][14][4];
#pragma unroll
    for (int i = 0; i < 2; i++)
#pragma unroll
        for (int j = 0; j < 14; j++)
#pragma unroll
            for (int q = 0; q < 4; q++) acc[i][j][q] = 0.f;

    // ldmatrix lane addressing
    int ri = lane & 7, mi = lane >> 3;
    uint32_t aOff = (uint32_t)((wm * 32 + ri + (mi & 1) * 8) * RS + (mi >> 1) * 16);
    uint32_t bOff = (uint32_t)(OFF_B + (wn * 112 + ri + ((mi >> 1) & 1) * 8) * RS + (mi & 1) * 16);

    // ---- cp.async stage issue: 2304 16B chunks, 18 per thread ----
    auto issue = [&](int c, int buf) {
        uint32_t st = sb + buf * STAGE;
        size_t kb2 = (size_t)(kbase + c * 32) * 2;
#pragma unroll
        for (int i = 0; i < 18; i++) {
            int t = tid + i * GT;
            uint32_t sa;
            const char* gp;
            if (t < 512) {
                int arr = t >> 8, rem = t & 255, r = rem >> 2, q = rem & 3;
                sa = st + arr * A_ARR + r * RS + q * 16;
                gp = gA[arr] + (size_t)(m0 + r) * (KPAD * 2) + kb2 + q * 16;
            } else {
                int t2 = t - 512;
                int arr = t2 / 896, rem = t2 % 896, r = rem >> 2, q = rem & 3;
                sa = st + OFF_B + arr * B_ARR + r * RS + q * 16;
                gp = gB[arr] + (size_t)r * (KPAD * 2) + kb2 + q * 16;
            }
            cpasync16(sa, gp);
        }
        asm volatile("cp.async.commit_group;");
    };

    issue(0, 0);
    for (int c = 0; c < NCHUNK; c++) {
        int buf = c & 1;
        if (c + 1 < NCHUNK) {
            issue(c + 1, buf ^ 1);
            asm volatile("cp.async.wait_group 1;");
        } else {
            asm volatile("cp.async.wait_group 0;");
        }
        __syncthreads();

        uint32_t st = sb + buf * STAGE;
#pragma unroll
        for (int kk = 0; kk < 2; kk++) {
            uint32_t ka = st + aOff + kk * 32;
            uint32_t ah0[4], ah1[4], al0[4], al1[4];
            ldsm4(ah0, ka);
            ldsm4(ah1, ka + 16 * RS);
            ldsm4(al0, ka + A_ARR);
            ldsm4(al1, ka + A_ARR + 16 * RS);
            uint32_t kb = st + bOff + kk * 32;
#pragma unroll
            for (int nf = 0; nf < 7; nf++) {
                uint32_t bh[4], bl[4];
                ldsm4(bh, kb + nf * (16 * RS));
                ldsm4(bl, kb + nf * (16 * RS) + B_ARR);
                // term AhBh
                mma16816(acc[0][2 * nf],     ah0, bh[0], bh[1]);
                mma16816(acc[1][2 * nf],     ah1, bh[0], bh[1]);
                mma16816(acc[0][2 * nf + 1], ah0, bh[2], bh[3]);
                mma16816(acc[1][2 * nf + 1], ah1, bh[2], bh[3]);
                // term AhBl
                mma16816(acc[0][2 * nf],     ah0, bl[0], bl[1]);
                mma16816(acc[1][2 * nf],     ah1, bl[0], bl[1]);
                mma16816(acc[0][2 * nf + 1], ah0, bl[2], bl[3]);
                mma16816(acc[1][2 * nf + 1], ah1, bl[2], bl[3]);
                // term AlBh
                mma16816(acc[0][2 * nf],     al0, bh[0], bh[1]);
                mma16816(acc[1][2 * nf],     al1, bh[0], bh[1]);
                mma16816(acc[0][2 * nf + 1], al0, bh[2], bh[3]);
                mma16816(acc[1][2 * nf + 1], al1, bh[2], bh[3]);
            }
        }
        __syncthreads();
    }

    // ---- epilogue: atomicAdd partial sums (out pre-initialized with bias) ----
    int g = lane >> 2, tg = lane & 3;
#pragma unroll
    for (int mf = 0; mf < 2; mf++) {
        int r0 = m0 + wm * 32 + mf * 16 + g;
        int r1 = r0 + 8;
#pragma unroll
        for (int nf = 0; nf < 14; nf++) {
            int col = wn * 112 + nf * 8 + tg * 2;
            if (col < DD) {
                if (r0 < NN) {
                    atomicAdd(&out[(size_t)r0 * DD + col],     acc[mf][nf][0]);
                    atomicAdd(&out[(size_t)r0 * DD + col + 1], acc[mf][nf][1]);
                }
                if (r1 < NN) {
                    atomicAdd(&out[(size_t)r1 * DD + col],     acc[mf][nf][2]);
                    atomicAdd(&out[(size_t)r1 * DD + col + 1], acc[mf][nf][3]);
                }
            }
        }
    }
}

extern "C" void kernel_launch(void* const* d_in, const int* in_sizes, int n_in,
                              void* d_out, int out_size) {
    const float* x      = (const float*)d_in[0];
    const float* weight = (const float*)d_in[1];
    const float* coeff  = (const float*)d_in[2];
    const float* selfw  = (const float*)d_in[3];
    const float* bias   = (const float*)d_in[4];
    const int*   eidx   = (const int*)d_in[5];
    const int*   etype  = (const int*)d_in[6];
    float*       out    = (float*)d_out;

    cudaFuncSetAttribute(k_gemm, cudaFuncAttributeMaxDynamicSharedMemorySize, SMEM_G);

    k_zero_deg<<<(NN + 255) / 256, 256>>>();
    k_count<<<(EE + 255) / 256, 256>>>(eidx);
    k_scan<<<1, 1024>>>();
    k_fill<<<(EE + 255) / 256, 256>>>(eidx, etype);
    k_prep_w<<<(DD * KPAD + 255) / 256, 256>>>(weight, selfw);
    k_agg<<<NN, AGG_T>>>(x, coeff);
    k_init<<<(NN * DD + 255) / 256, 256>>>(bias, out);
    k_gemm<<<dim3(MPAD / 64, 2), GT, SMEM_G>>>(out);
}

// round 5
// speedup vs baseline: 2.4702x; 1.0348x over previous
#include <cuda_runtime.h>
#include <cuda_bf16.h>
#include <cstdint>

#define NN   10000
#define EE   320000
#define RR   460
#define BB   30
#define DD   200
#define KTOT 6200
#define KPAD 6208            // multiple of 64
#define MPAD 10112           // 79 * 128
#define NPAD 224             // multiple of 16
#define NCHTOT 194           // KPAD / 32

// ---- device scratch (zero-initialized; pad rows/cols never written -> stay 0) ----
__device__ __nv_bfloat16 g_Ah[(size_t)MPAD * KPAD];
__device__ __nv_bfloat16 g_Al[(size_t)MPAD * KPAD];
__device__ __nv_bfloat16 g_Bh[(size_t)NPAD * KPAD];   // B^T: n-major rows, k cols
__device__ __nv_bfloat16 g_Bl[(size_t)NPAD * KPAD];
__device__ int g_deg[NN];
__device__ int g_off[NN + 1];
__device__ int g_cur[NN];
__device__ int g_esrc[EE];
__device__ int g_erel[EE];

// ---------------- helpers ----------------
__device__ __forceinline__ uint32_t smem_u32(const void* p) {
    uint32_t a;
    asm("{ .reg .u64 t; cvta.to.shared.u64 t, %1; cvt.u32.u64 %0, t; }" : "=r"(a) : "l"(p));
    return a;
}
__device__ __forceinline__ void ldsm4(uint32_t* r, uint32_t a) {
    asm volatile("ldmatrix.sync.aligned.m8n8.x4.shared.b16 {%0,%1,%2,%3}, [%4];"
                 : "=r"(r[0]), "=r"(r[1]), "=r"(r[2]), "=r"(r[3]) : "r"(a));
}
__device__ __forceinline__ void mma16816(float* c, const uint32_t* a, uint32_t b0, uint32_t b1) {
    asm volatile(
        "mma.sync.aligned.m16n8k16.row.col.f32.bf16.bf16.f32 "
        "{%0,%1,%2,%3}, {%4,%5,%6,%7}, {%8,%9}, {%0,%1,%2,%3};"
        : "+f"(c[0]), "+f"(c[1]), "+f"(c[2]), "+f"(c[3])
        : "r"(a[0]), "r"(a[1]), "r"(a[2]), "r"(a[3]), "r"(b0), "r"(b1));
}
__device__ __forceinline__ void cpasync16(uint32_t sa, const void* gp) {
    asm volatile("cp.async.cg.shared.global [%0], [%1], 16;" :: "r"(sa), "l"(gp));
}

// ---------------- CSR build ----------------
__global__ void k_zero_deg() {
    int i = blockIdx.x * blockDim.x + threadIdx.x;
    if (i < NN) g_deg[i] = 0;
}
__global__ void k_count(const int* __restrict__ eidx) {
    int e = blockIdx.x * blockDim.x + threadIdx.x;
    if (e < EE) atomicAdd(&g_deg[eidx[EE + e]], 1);
}
// 256 threads, 40 serial elems each + one 256-wide scan
__global__ void k_scan() {
    __shared__ int part[256];
    int t = threadIdx.x;
    const int PER = 40;  // 256*40 = 10240 >= NN
    int base = t * PER;
    int s = 0;
    for (int i = 0; i < PER; i++) {
        int idx = base + i;
        if (idx < NN) s += g_deg[idx];
    }
    part[t] = s;
    __syncthreads();
    for (int off = 1; off < 256; off <<= 1) {
        int v = (t >= off) ? part[t - off] : 0;
        __syncthreads();
        part[t] += v;
        __syncthreads();
    }
    int run = (t == 0) ? 0 : part[t - 1];
    for (int i = 0; i < PER; i++) {
        int idx = base + i;
        if (idx < NN) {
            g_off[idx] = run;
            g_cur[idx] = run;
            run += g_deg[idx];
        }
    }
    if (t == 255) g_off[NN] = part[255];
}
__global__ void k_fill(const int* __restrict__ eidx, const int* __restrict__ etype) {
    int e = blockIdx.x * blockDim.x + threadIdx.x;
    if (e < EE) {
        int t = eidx[EE + e];
        int p = atomicAdd(&g_cur[t], 1);
        g_esrc[p] = eidx[e];
        g_erel[p] = etype[e];
    }
}

// ---------------- weight transpose + bf16 split (coalesced tiled) ----------------
// grid: (KPAD/32, 7) ; block 32x8 ; tile 32k x 32n
__global__ void k_prep_w(const float* __restrict__ w, const float* __restrict__ sw) {
    __shared__ float tile[32][33];
    int k0 = blockIdx.x * 32;
    int n0 = blockIdx.y * 32;
    int tx = threadIdx.x, ty = threadIdx.y;
#pragma unroll
    for (int s = 0; s < 4; s++) {
        int k = k0 + ty + 8 * s;
        int n = n0 + tx;
        float v = 0.f;
        if (n < DD) {
            if (k < 6000)      v = w[(size_t)k * DD + n];
            else if (k < KTOT) v = sw[(size_t)(k - 6000) * DD + n];
        }
        tile[ty + 8 * s][tx] = v;
    }
    __syncthreads();
#pragma unroll
    for (int s = 0; s < 4; s++) {
        int n = n0 + ty + 8 * s;
        int k = k0 + tx;
        if (n < DD) {
            float v = tile[tx][ty + 8 * s];
            __nv_bfloat16 h = __float2bfloat16(v);
            g_Bh[(size_t)n * KPAD + k] = h;
            g_Bl[(size_t)n * KPAD + k] = __float2bfloat16(v - __bfloat162float(h));
        }
    }
}

// ---------------- out = bias (broadcast) ----------------
__global__ void k_init(const float* __restrict__ bias, float* __restrict__ out) {
    int i = blockIdx.x * blockDim.x + threadIdx.x;
    if (i < NN * DD) out[i] = bias[i % DD];
}

// ---------------- aggregation -> bf16 hi/lo A rows ----------------
#define AGG_T 224
#define EB    32
__global__ __launch_bounds__(AGG_T) void k_agg(const float* __restrict__ x,
                                               const float* __restrict__ coeff) {
    __shared__ float sC[EB][32];    // coeff padded to 32 (cols 30,31 = 0)
    __shared__ int   sSrc[EB];
    __shared__ int   sRel[EB];
    int n   = blockIdx.x;
    int tid = threadIdx.x;
    int start = g_off[n], end = g_off[n + 1];
    int deg = end - start;
    float inv = 1.0f / (float)(deg > 1 ? deg : 1);

    float acc[32];
#pragma unroll
    for (int b = 0; b < 32; b++) acc[b] = 0.f;

    int d = tid;
    bool active = d < DD;
    for (int e0 = start; e0 < end; e0 += EB) {
        int nb = min(EB, end - e0);
        __syncthreads();
        if (tid < nb) { sSrc[tid] = g_esrc[e0 + tid]; sRel[tid] = g_erel[e0 + tid]; }
        __syncthreads();
        for (int i = tid; i < nb * 32; i += AGG_T) {
            int le = i >> 5, b = i & 31;
            sC[le][b] = (b < BB) ? coeff[sRel[le] * BB + b] : 0.f;
        }
        __syncthreads();
        if (active) {
            int le = 0;
            for (; le + 4 <= nb; le += 4) {
                float xv0 = x[(size_t)sSrc[le]     * DD + d];
                float xv1 = x[(size_t)sSrc[le + 1] * DD + d];
                float xv2 = x[(size_t)sSrc[le + 2] * DD + d];
                float xv3 = x[(size_t)sSrc[le + 3] * DD + d];
                const float4* c0 = (const float4*)sC[le];
                const float4* c1 = (const float4*)sC[le + 1];
                const float4* c2 = (const float4*)sC[le + 2];
                const float4* c3 = (const float4*)sC[le + 3];
#pragma unroll
                for (int q = 0; q < 8; q++) {
                    float4 a0 = c0[q], a1 = c1[q], a2 = c2[q], a3 = c3[q];
                    acc[4*q+0] = fmaf(a0.x, xv0, acc[4*q+0]);
                    acc[4*q+1] = fmaf(a0.y, xv0, acc[4*q+1]);
                    acc[4*q+2] = fmaf(a0.z, xv0, acc[4*q+2]);
                    acc[4*q+3] = fmaf(a0.w, xv0, acc[4*q+3]);
                    acc[4*q+0] = fmaf(a1.x, xv1, acc[4*q+0]);
                    acc[4*q+1] = fmaf(a1.y, xv1, acc[4*q+1]);
                    acc[4*q+2] = fmaf(a1.z, xv1, acc[4*q+2]);
                    acc[4*q+3] = fmaf(a1.w, xv1, acc[4*q+3]);
                    acc[4*q+0] = fmaf(a2.x, xv2, acc[4*q+0]);
                    acc[4*q+1] = fmaf(a2.y, xv2, acc[4*q+1]);
                    acc[4*q+2] = fmaf(a2.z, xv2, acc[4*q+2]);
                    acc[4*q+3] = fmaf(a2.w, xv2, acc[4*q+3]);
                    acc[4*q+0] = fmaf(a3.x, xv3, acc[4*q+0]);
                    acc[4*q+1] = fmaf(a3.y, xv3, acc[4*q+1]);
                    acc[4*q+2] = fmaf(a3.z, xv3, acc[4*q+2]);
                    acc[4*q+3] = fmaf(a3.w, xv3, acc[4*q+3]);
                }
            }
            for (; le < nb; le++) {
                float xv = x[(size_t)sSrc[le] * DD + d];
                const float4* cp = (const float4*)sC[le];
#pragma unroll
                for (int q = 0; q < 8; q++) {
                    float4 a = cp[q];
                    acc[4*q+0] = fmaf(a.x, xv, acc[4*q+0]);
                    acc[4*q+1] = fmaf(a.y, xv, acc[4*q+1]);
                    acc[4*q+2] = fmaf(a.z, xv, acc[4*q+2]);
                    acc[4*q+3] = fmaf(a.w, xv, acc[4*q+3]);
                }
            }
        }
    }
    if (active) {
        size_t row = (size_t)n * KPAD;
#pragma unroll
        for (int b = 0; b < BB; b++) {
            float v = acc[b] * inv;
            __nv_bfloat16 h = __float2bfloat16(v);
            g_Ah[row + b * DD + d] = h;
            g_Al[row + b * DD + d] = __float2bfloat16(v - __bfloat162float(h));
        }
        float v = x[(size_t)n * DD + d];
        __nv_bfloat16 h = __float2bfloat16(v);
        g_Ah[row + 6000 + d] = h;
        g_Al[row + 6000 + d] = __float2bfloat16(v - __bfloat162float(h));
    }
}

// ---------------- bf16 3-term MMA GEMM, m128 x n224, K-split 4, atomic epilogue ----------------
// CTA: 256 thr (8 warps), warp tile m32 x n112. K block = 32 elems per chunk.
#define GT     256
#define RS     80            // 64B data + 16B pad per row (conflict-free ldmatrix)
#define A_ARR  10240         // 128*RS
#define B_ARR  17920         // 224*RS
#define OFF_B  20480         // 2*A_ARR
#define STAGE  56320         // 2*A_ARR + 2*B_ARR
#define SMEM_G (2 * STAGE)   // 112640

__global__ __launch_bounds__(GT, 1) void k_gemm(float* __restrict__ out) {
    extern __shared__ char smem[];
    uint32_t sb = smem_u32(smem);
    int tid = threadIdx.x, lane = tid & 31, wid = tid >> 5;
    int m0 = blockIdx.x * 128;
    int by = blockIdx.y;
    int c0 = (NCHTOT * by) >> 2;
    int c1 = (NCHTOT * (by + 1)) >> 2;
    int wm = wid & 3, wn = wid >> 2;

    const char* gA[2] = {(const char*)g_Ah, (const char*)g_Al};
    const char* gB[2] = {(const char*)g_Bh, (const char*)g_Bl};

    float acc[2][14][4];
#pragma unroll
    for (int i = 0; i < 2; i++)
#pragma unroll
        for (int j = 0; j < 14; j++)
#pragma unroll
            for (int q = 0; q < 4; q++) acc[i][j][q] = 0.f;

    int ri = lane & 7, mi = lane >> 3;
    uint32_t aOff = (uint32_t)((wm * 32 + ri + (mi & 1) * 8) * RS + (mi >> 1) * 16);
    uint32_t bOff = (uint32_t)(OFF_B + (wn * 112 + ri + ((mi >> 1) & 1) * 8) * RS + (mi & 1) * 16);

    // ---- cp.async stage issue: 2816 16B chunks, 11 per thread ----
    auto issue = [&](int c, int buf) {
        uint32_t st = sb + buf * STAGE;
        size_t kb2 = (size_t)c * 64;   // 32 bf16 = 64 bytes
#pragma unroll
        for (int i = 0; i < 11; i++) {
            int t = tid + i * GT;
            uint32_t sa;
            const char* gp;
            if (t < 1024) {
                int arr = t >> 9, rem = t & 511, r = rem >> 2, q = rem & 3;
                sa = st + arr * A_ARR + r * RS + q * 16;
                gp = gA[arr] + (size_t)(m0 + r) * (KPAD * 2) + kb2 + q * 16;
            } else {
                int t2 = t - 1024;
                int arr = t2 / 896, rem = t2 % 896, r = rem >> 2, q = rem & 3;
                sa = st + OFF_B + arr * B_ARR + r * RS + q * 16;
                gp = gB[arr] + (size_t)r * (KPAD * 2) + kb2 + q * 16;
            }
            cpasync16(sa, gp);
        }
        asm volatile("cp.async.commit_group;");
    };

    issue(c0, 0);
    for (int c = c0; c < c1; c++) {
        int buf = (c - c0) & 1;
        if (c + 1 < c1) {
            issue(c + 1, buf ^ 1);
            asm volatile("cp.async.wait_group 1;");
        } else {
            asm volatile("cp.async.wait_group 0;");
        }
        __syncthreads();

        uint32_t st = sb + buf * STAGE;
#pragma unroll
        for (int kk = 0; kk < 2; kk++) {
            uint32_t ka = st + aOff + kk * 32;
            uint32_t ah0[4], ah1[4], al0[4], al1[4];
            ldsm4(ah0, ka);
            ldsm4(ah1, ka + 16 * RS);
            ldsm4(al0, ka + A_ARR);
            ldsm4(al1, ka + A_ARR + 16 * RS);
            uint32_t kb = st + bOff + kk * 32;
#pragma unroll
            for (int nf = 0; nf < 7; nf++) {
                uint32_t bh[4], bl[4];
                ldsm4(bh, kb + nf * (16 * RS));
                ldsm4(bl, kb + nf * (16 * RS) + B_ARR);
                mma16816(acc[0][2 * nf],     ah0, bh[0], bh[1]);
                mma16816(acc[1][2 * nf],     ah1, bh[0], bh[1]);
                mma16816(acc[0][2 * nf + 1], ah0, bh[2], bh[3]);
                mma16816(acc[1][2 * nf + 1], ah1, bh[2], bh[3]);
                mma16816(acc[0][2 * nf],     ah0, bl[0], bl[1]);
                mma16816(acc[1][2 * nf],     ah1, bl[0], bl[1]);
                mma16816(acc[0][2 * nf + 1], ah0, bl[2], bl[3]);
                mma16816(acc[1][2 * nf + 1], ah1, bl[2], bl[3]);
                mma16816(acc[0][2 * nf],     al0, bh[0], bh[1]);
                mma16816(acc[1][2 * nf],     al1, bh[0], bh[1]);
                mma16816(acc[0][2 * nf + 1], al0, bh[2], bh[3]);
                mma16816(acc[1][2 * nf + 1], al1, bh[2], bh[3]);
            }
        }
        __syncthreads();
    }

    // ---- epilogue: atomicAdd partial sums (out pre-initialized with bias) ----
    int g = lane >> 2, tg = lane & 3;
#pragma unroll
    for (int mf = 0; mf < 2; mf++) {
        int r0 = m0 + wm * 32 + mf * 16 + g;
        int r1 = r0 + 8;
#pragma unroll
        for (int nf = 0; nf < 14; nf++) {
            int col = wn * 112 + nf * 8 + tg * 2;
            if (col < DD) {
                if (r0 < NN) {
                    atomicAdd(&out[(size_t)r0 * DD + col],     acc[mf][nf][0]);
                    atomicAdd(&out[(size_t)r0 * DD + col + 1], acc[mf][nf][1]);
                }
                if (r1 < NN) {
                    atomicAdd(&out[(size_t)r1 * DD + col],     acc[mf][nf][2]);
                    atomicAdd(&out[(size_t)r1 * DD + col + 1], acc[mf][nf][3]);
                }
            }
        }
    }
}

extern "C" void kernel_launch(void* const* d_in, const int* in_sizes, int n_in,
                              void* d_out, int out_size) {
    const float* x      = (const float*)d_in[0];
    const float* weight = (const float*)d_in[1];
    const float* coeff  = (const float*)d_in[2];
    const float* selfw  = (const float*)d_in[3];
    const float* bias   = (const float*)d_in[4];
    const int*   eidx   = (const int*)d_in[5];
    const int*   etype  = (const int*)d_in[6];
    float*       out    = (float*)d_out;

    cudaFuncSetAttribute(k_gemm, cudaFuncAttributeMaxDynamicSharedMemorySize, SMEM_G);

    k_zero_deg<<<(NN + 255) / 256, 256>>>();
    k_count<<<(EE + 255) / 256, 256>>>(eidx);
    k_scan<<<1, 256>>>();
    k_fill<<<(EE + 255) / 256, 256>>>(eidx, etype);
    k_prep_w<<<dim3(KPAD / 32, 7), dim3(32, 8)>>>(weight, selfw);
    k_agg<<<NN, AGG_T>>>(x, coeff);
    k_init<<<(NN * DD + 255) / 256, 256>>>(bias, out);
    k_gemm<<<dim3(MPAD / 128, 4), GT, SMEM_G>>>(out);
}

// round 7
// speedup vs baseline: 2.7577x; 1.1164x over previous
#include <cuda_runtime.h>
#include <cuda_bf16.h>
#include <cstdint>

#define NN   10000
#define EE   320000
#define RR   460
#define BB   30
#define DD   200
#define KTOT 6200
#define KPAD 6208            // multiple of 64
#define MPAD 10112           // 79 * 128
#define NPAD 224             // multiple of 16
#define NCHTOT 194           // KPAD / 32
#define NKSL  16             // K slices
#define NMT   79             // m tiles
#define NUNITS (NMT * NKSL)  // 1264

// ---- device scratch (zero-initialized; pad rows/cols never written -> stay 0) ----
__device__ __nv_bfloat16 g_Ah[(size_t)MPAD * KPAD];
__device__ __nv_bfloat16 g_Al[(size_t)MPAD * KPAD];
__device__ __nv_bfloat16 g_Bh[(size_t)NPAD * KPAD];   // B^T: n-major rows, k cols
__device__ __nv_bfloat16 g_Bl[(size_t)NPAD * KPAD];
__device__ int g_deg[NN];
__device__ int g_off[NN + 1];
__device__ int g_cur[NN];
__device__ int g_esrc[EE];
__device__ int g_erel[EE];

// ---------------- helpers ----------------
__device__ __forceinline__ uint32_t smem_u32(const void* p) {
    uint32_t a;
    asm("{ .reg .u64 t; cvta.to.shared.u64 t, %1; cvt.u32.u64 %0, t; }" : "=r"(a) : "l"(p));
    return a;
}
__device__ __forceinline__ void ldsm4(uint32_t* r, uint32_t a) {
    asm volatile("ldmatrix.sync.aligned.m8n8.x4.shared.b16 {%0,%1,%2,%3}, [%4];"
                 : "=r"(r[0]), "=r"(r[1]), "=r"(r[2]), "=r"(r[3]) : "r"(a));
}
__device__ __forceinline__ void mma16816(float* c, const uint32_t* a, uint32_t b0, uint32_t b1) {
    asm volatile(
        "mma.sync.aligned.m16n8k16.row.col.f32.bf16.bf16.f32 "
        "{%0,%1,%2,%3}, {%4,%5,%6,%7}, {%8,%9}, {%0,%1,%2,%3};"
        : "+f"(c[0]), "+f"(c[1]), "+f"(c[2]), "+f"(c[3])
        : "r"(a[0]), "r"(a[1]), "r"(a[2]), "r"(a[3]), "r"(b0), "r"(b1));
}
__device__ __forceinline__ void cpasync16(uint32_t sa, const void* gp) {
    asm volatile("cp.async.cg.shared.global [%0], [%1], 16;" :: "r"(sa), "l"(gp));
}

// ---------------- CSR build ----------------
__global__ void k_count(const int* __restrict__ eidx) {
    int e = blockIdx.x * blockDim.x + threadIdx.x;
    if (e < EE) atomicAdd(&g_deg[eidx[EE + e]], 1);
}
// 256 threads, 40 serial elems each + one 256-wide scan
__global__ void k_scan() {
    __shared__ int part[256];
    int t = threadIdx.x;
    const int PER = 40;
    int base = t * PER;
    int s = 0;
    for (int i = 0; i < PER; i++) {
        int idx = base + i;
        if (idx < NN) s += g_deg[idx];
    }
    part[t] = s;
    __syncthreads();
    for (int off = 1; off < 256; off <<= 1) {
        int v = (t >= off) ? part[t - off] : 0;
        __syncthreads();
        part[t] += v;
        __syncthreads();
    }
    int run = (t == 0) ? 0 : part[t - 1];
    for (int i = 0; i < PER; i++) {
        int idx = base + i;
        if (idx < NN) {
            g_off[idx] = run;
            g_cur[idx] = run;
            run += g_deg[idx];
        }
    }
    if (t == 255) g_off[NN] = part[255];
}
__global__ void k_fill(const int* __restrict__ eidx, const int* __restrict__ etype) {
    int e = blockIdx.x * blockDim.x + threadIdx.x;
    if (e < EE) {
        int t = eidx[EE + e];
        int p = atomicAdd(&g_cur[t], 1);
        g_esrc[p] = eidx[e];
        g_erel[p] = etype[e];
    }
}

// ---------------- weight transpose + bf16 split (coalesced tiled) ----------------
__global__ void k_prep_w(const float* __restrict__ w, const float* __restrict__ sw) {
    __shared__ float tile[32][33];
    int k0 = blockIdx.x * 32;
    int n0 = blockIdx.y * 32;
    int tx = threadIdx.x, ty = threadIdx.y;
#pragma unroll
    for (int s = 0; s < 4; s++) {
        int k = k0 + ty + 8 * s;
        int n = n0 + tx;
        float v = 0.f;
        if (n < DD) {
            if (k < 6000)      v = w[(size_t)k * DD + n];
            else if (k < KTOT) v = sw[(size_t)(k - 6000) * DD + n];
        }
        tile[ty + 8 * s][tx] = v;
    }
    __syncthreads();
#pragma unroll
    for (int s = 0; s < 4; s++) {
        int n = n0 + ty + 8 * s;
        int k = k0 + tx;
        if (n < DD) {
            float v = tile[tx][ty + 8 * s];
            __nv_bfloat16 h = __float2bfloat16(v);
            g_Bh[(size_t)n * KPAD + k] = h;
            g_Bl[(size_t)n * KPAD + k] = __float2bfloat16(v - __bfloat162float(h));
        }
    }
}

// ---------------- aggregation -> bf16 hi/lo A rows ----------------
#define AGG_T 224
#define EB    32
__global__ __launch_bounds__(AGG_T) void k_agg(const float* __restrict__ x,
                                               const float* __restrict__ coeff) {
    __shared__ float sC[EB][32];
    __shared__ int   sSrc[EB];
    __shared__ int   sRel[EB];
    int n   = blockIdx.x;
    int tid = threadIdx.x;
    int start = g_off[n], end = g_off[n + 1];
    int deg = end - start;
    float inv = 1.0f / (float)(deg > 1 ? deg : 1);

    float acc[32];
#pragma unroll
    for (int b = 0; b < 32; b++) acc[b] = 0.f;

    int d = tid;
    bool active = d < DD;
    for (int e0 = start; e0 < end; e0 += EB) {
        int nb = min(EB, end - e0);
        __syncthreads();
        if (tid < nb) { sSrc[tid] = g_esrc[e0 + tid]; sRel[tid] = g_erel[e0 + tid]; }
        __syncthreads();
        for (int i = tid; i < nb * 32; i += AGG_T) {
            int le = i >> 5, b = i & 31;
            sC[le][b] = (b < BB) ? coeff[sRel[le] * BB + b] : 0.f;
        }
        __syncthreads();
        if (active) {
            int le = 0;
            for (; le + 4 <= nb; le += 4) {
                float xv0 = x[(size_t)sSrc[le]     * DD + d];
                float xv1 = x[(size_t)sSrc[le + 1] * DD + d];
                float xv2 = x[(size_t)sSrc[le + 2] * DD + d];
                float xv3 = x[(size_t)sSrc[le + 3] * DD + d];
                const float4* c0 = (const float4*)sC[le];
                const float4* c1 = (const float4*)sC[le + 1];
                const float4* c2 = (const float4*)sC[le + 2];
                const float4* c3 = (const float4*)sC[le + 3];
#pragma unroll
                for (int q = 0; q < 8; q++) {
                    float4 a0 = c0[q], a1 = c1[q], a2 = c2[q], a3 = c3[q];
                    acc[4*q+0] = fmaf(a0.x, xv0, acc[4*q+0]);
                    acc[4*q+1] = fmaf(a0.y, xv0, acc[4*q+1]);
                    acc[4*q+2] = fmaf(a0.z, xv0, acc[4*q+2]);
                    acc[4*q+3] = fmaf(a0.w, xv0, acc[4*q+3]);
                    acc[4*q+0] = fmaf(a1.x, xv1, acc[4*q+0]);
                    acc[4*q+1] = fmaf(a1.y, xv1, acc[4*q+1]);
                    acc[4*q+2] = fmaf(a1.z, xv1, acc[4*q+2]);
                    acc[4*q+3] = fmaf(a1.w, xv1, acc[4*q+3]);
                    acc[4*q+0] = fmaf(a2.x, xv2, acc[4*q+0]);
                    acc[4*q+1] = fmaf(a2.y, xv2, acc[4*q+1]);
                    acc[4*q+2] = fmaf(a2.z, xv2, acc[4*q+2]);
                    acc[4*q+3] = fmaf(a2.w, xv2, acc[4*q+3]);
                    acc[4*q+0] = fmaf(a3.x, xv3, acc[4*q+0]);
                    acc[4*q+1] = fmaf(a3.y, xv3, acc[4*q+1]);
                    acc[4*q+2] = fmaf(a3.z, xv3, acc[4*q+2]);
                    acc[4*q+3] = fmaf(a3.w, xv3, acc[4*q+3]);
                }
            }
            for (; le < nb; le++) {
                float xv = x[(size_t)sSrc[le] * DD + d];
                const float4* cp = (const float4*)sC[le];
#pragma unroll
                for (int q = 0; q < 8; q++) {
                    float4 a = cp[q];
                    acc[4*q+0] = fmaf(a.x, xv, acc[4*q+0]);
                    acc[4*q+1] = fmaf(a.y, xv, acc[4*q+1]);
                    acc[4*q+2] = fmaf(a.z, xv, acc[4*q+2]);
                    acc[4*q+3] = fmaf(a.w, xv, acc[4*q+3]);
                }
            }
        }
    }
    if (active) {
        size_t row = (size_t)n * KPAD;
#pragma unroll
        for (int b = 0; b < BB; b++) {
            float v = acc[b] * inv;
            __nv_bfloat16 h = __float2bfloat16(v);
            g_Ah[row + b * DD + d] = h;
            g_Al[row + b * DD + d] = __float2bfloat16(v - __bfloat162float(h));
        }
        float v = x[(size_t)n * DD + d];
        __nv_bfloat16 h = __float2bfloat16(v);
        g_Ah[row + 6000 + d] = h;
        g_Al[row + 6000 + d] = __float2bfloat16(v - __bfloat162float(h));
    }
}

// ---------------- persistent bf16 3-term MMA GEMM ----------------
// 152 CTAs, 1264 units (79 mtiles x 16 kslices), m128 x n224, atomic epilogue.
#define GT     256
#define RS     80            // 64B data + 16B pad per row (conflict-free ldmatrix)
#define A_ARR  10240         // 128*RS
#define B_ARR  17920         // 224*RS
#define OFF_B  20480         // 2*A_ARR
#define STAGE  56320         // 2*A_ARR + 2*B_ARR
#define SMEM_G (2 * STAGE)   // 112640
#define GRID_G 152

__global__ __launch_bounds__(GT, 1) void k_gemm(const float* __restrict__ bias,
                                                float* __restrict__ out) {
    extern __shared__ char smem[];
    uint32_t sb = smem_u32(smem);
    int tid = threadIdx.x, lane = tid & 31, wid = tid >> 5;
    int wm = wid & 3, wn = wid >> 2;

    const char* gA[2] = {(const char*)g_Ah, (const char*)g_Al};
    const char* gB[2] = {(const char*)g_Bh, (const char*)g_Bl};

    int ri = lane & 7, mi = lane >> 3;
    uint32_t aOff = (uint32_t)((wm * 32 + ri + (mi & 1) * 8) * RS + (mi >> 1) * 16);
    uint32_t bOff = (uint32_t)(OFF_B + (wn * 112 + ri + ((mi >> 1) & 1) * 8) * RS + (mi & 1) * 16);
    int g = lane >> 2, tg = lane & 3;

    for (int u = blockIdx.x; u < NUNITS; u += GRID_G) {
        int mt = u % NMT;
        int ks = u / NMT;
        int m0 = mt * 128;
        int c0 = (NCHTOT * ks) >> 4;
        int c1 = (NCHTOT * (ks + 1)) >> 4;

        float acc[2][14][4];
#pragma unroll
        for (int i = 0; i < 2; i++)
#pragma unroll
            for (int j = 0; j < 14; j++)
#pragma unroll
                for (int q = 0; q < 4; q++) acc[i][j][q] = 0.f;

        auto issue = [&](int c, int buf) {
            uint32_t st = sb + buf * STAGE;
            size_t kb2 = (size_t)c * 64;
#pragma unroll
            for (int i = 0; i < 11; i++) {
                int t = tid + i * GT;
                uint32_t sa;
                const char* gp;
                if (t < 1024) {
                    int arr = t >> 9, rem = t & 511, r = rem >> 2, q = rem & 3;
                    sa = st + arr * A_ARR + r * RS + q * 16;
                    gp = gA[arr] + (size_t)(m0 + r) * (KPAD * 2) + kb2 + q * 16;
                } else {
                    int t2 = t - 1024;
                    int arr = t2 / 896, rem = t2 % 896, r = rem >> 2, q = rem & 3;
                    sa = st + OFF_B + arr * B_ARR + r * RS + q * 16;
                    gp = gB[arr] + (size_t)r * (KPAD * 2) + kb2 + q * 16;
                }
                cpasync16(sa, gp);
            }
            asm volatile("cp.async.commit_group;");
        };

        issue(c0, 0);
        for (int c = c0; c < c1; c++) {
            int buf = (c - c0) & 1;
            if (c + 1 < c1) {
                issue(c + 1, buf ^ 1);
                asm volatile("cp.async.wait_group 1;");
            } else {
                asm volatile("cp.async.wait_group 0;");
            }
            __syncthreads();

            uint32_t st = sb + buf * STAGE;
#pragma unroll
            for (int kk = 0; kk < 2; kk++) {
                uint32_t ka = st + aOff + kk * 32;
                uint32_t ah0[4], ah1[4], al0[4], al1[4];
                ldsm4(ah0, ka);
                ldsm4(ah1, ka + 16 * RS);
                ldsm4(al0, ka + A_ARR);
                ldsm4(al1, ka + A_ARR + 16 * RS);
                uint32_t kb = st + bOff + kk * 32;
#pragma unroll
                for (int nf = 0; nf < 7; nf++) {
                    uint32_t bh[4], bl[4];
                    ldsm4(bh, kb + nf * (16 * RS));
                    ldsm4(bl, kb + nf * (16 * RS) + B_ARR);
                    mma16816(acc[0][2 * nf],     ah0, bh[0], bh[1]);
                    mma16816(acc[1][2 * nf],     ah1, bh[0], bh[1]);
                    mma16816(acc[0][2 * nf + 1], ah0, bh[2], bh[3]);
                    mma16816(acc[1][2 * nf + 1], ah1, bh[2], bh[3]);
                    mma16816(acc[0][2 * nf],     ah0, bl[0], bl[1]);
                    mma16816(acc[1][2 * nf],     ah1, bl[0], bl[1]);
                    mma16816(acc[0][2 * nf + 1], ah0, bl[2], bl[3]);
                    mma16816(acc[1][2 * nf + 1], ah1, bl[2], bl[3]);
                    mma16816(acc[0][2 * nf],     al0, bh[0], bh[1]);
                    mma16816(acc[1][2 * nf],     al1, bh[0], bh[1]);
                    mma16816(acc[0][2 * nf + 1], al0, bh[2], bh[3]);
                    mma16816(acc[1][2 * nf + 1], al1, bh[2], bh[3]);
                }
            }
            __syncthreads();
        }

        // epilogue: atomicAdd partials; kslice 0 also adds bias (out memset to 0)
#pragma unroll
        for (int mf = 0; mf < 2; mf++) {
            int r0 = m0 + wm * 32 + mf * 16 + g;
            int r1 = r0 + 8;
#pragma unroll
            for (int nf = 0; nf < 14; nf++) {
                int col = wn * 112 + nf * 8 + tg * 2;
                if (col < DD) {
                    float b0 = 0.f, b1 = 0.f;
                    if (ks == 0) { b0 = bias[col]; b1 = bias[col + 1]; }
                    if (r0 < NN) {
                        atomicAdd(&out[(size_t)r0 * DD + col],     acc[mf][nf][0] + b0);
                        atomicAdd(&out[(size_t)r0 * DD + col + 1], acc[mf][nf][1] + b1);
                    }
                    if (r1 < NN) {
                        atomicAdd(&out[(size_t)r1 * DD + col],     acc[mf][nf][2] + b0);
                        atomicAdd(&out[(size_t)r1 * DD + col + 1], acc[mf][nf][3] + b1);
                    }
                }
            }
        }
    }
}

extern "C" void kernel_launch(void* const* d_in, const int* in_sizes, int n_in,
                              void* d_out, int out_size) {
    const float* x      = (const float*)d_in[0];
    const float* weight = (const float*)d_in[1];
    const float* coeff  = (const float*)d_in[2];
    const float* selfw  = (const float*)d_in[3];
    const float* bias   = (const float*)d_in[4];
    const int*   eidx   = (const int*)d_in[5];
    const int*   etype  = (const int*)d_in[6];
    float*       out    = (float*)d_out;

    static void* p_deg = nullptr;
    if (!p_deg) {
        cudaGetSymbolAddress(&p_deg, g_deg);
        cudaFuncSetAttribute(k_gemm, cudaFuncAttributeMaxDynamicSharedMemorySize, SMEM_G);
    }

    cudaMemsetAsync(p_deg, 0, NN * sizeof(int));
    cudaMemsetAsync(out, 0, (size_t)NN * DD * sizeof(float));
    k_count<<<(EE + 255) / 256, 256>>>(eidx);
    k_scan<<<1, 256>>>();
    k_fill<<<(EE + 255) / 256, 256>>>(eidx, etype);
    k_agg<<<NN, AGG_T>>>(x, coeff);
    k_prep_w<<<dim3(KPAD / 32, 7), dim3(32, 8)>>>(weight, selfw);
    k_gemm<<<GRID_G, GT, SMEM_G>>>(bias, out);
}